// round 5
// baseline (speedup 1.0000x reference)
#include <cuda_runtime.h>
#include <cuda_fp16.h>
#include <cstdint>

#define DEV_INLINE __device__ __forceinline__

static constexpr int NDIM   = 1024;   // DCT length (axis 1)
static constexpr int NBATCH = 32;

// GEMM tiling (portable mma.sync path — tcgen05 rejected by compute_103 PTX target)
static constexpr int BM = 128;        // DCT output rows per CTA
static constexpr int BN = 128;        // (b,m) columns per CTA
static constexpr int BK = 64;         // K per chunk (64 fp16 = 128 B = SW128 row)
static constexpr int NCHUNK = NDIM / BK;   // 16
static constexpr int STAGES = 3;
static constexpr int THREADS = 128;   // 4 warps: 2 (m) x 2 (n), warp tile 64x64

static constexpr int A_STAGE_BYTES = BM * 128;              // 16 KB
static constexpr int STAGE_BYTES   = 2 * A_STAGE_BYTES;     // 32 KB (A + B)
static constexpr int SMEM_TOTAL    = STAGES * STAGE_BYTES;  // 96 KB (also covers epilogue staging 67.6 KB)

// Scratch (allocation-free rule: __device__ globals)
__device__ __half d_C[NDIM * NDIM];                        // DCT matrix fp16, [k][j]
__device__ __half d_xt[(size_t)NBATCH * NDIM * NDIM];      // x transposed+fp16, [b][m][j]

// ---------------------------------------------------------------- helpers
DEV_INLINE uint32_t smem_u32(const void* p) {
    uint32_t a;
    asm("{ .reg .u64 t; cvta.to.shared.u64 t, %1; cvt.u32.u64 %0, t; }" : "=r"(a) : "l"(p));
    return a;
}
DEV_INLINE void cp16(uint32_t saddr, const void* g) {
    asm volatile("cp.async.cg.shared.global [%0], [%1], 16;" :: "r"(saddr), "l"(g));
}
DEV_INLINE void cp_commit() { asm volatile("cp.async.commit_group;"); }
template <int N> DEV_INLINE void cp_wait() { asm volatile("cp.async.wait_group %0;" :: "n"(N)); }
DEV_INLINE uint32_t swz(uint32_t off) { return off ^ ((off >> 3) & 0x70); }

DEV_INLINE void ldsm4(uint32_t* r, uint32_t addr) {
    asm volatile("ldmatrix.sync.aligned.m8n8.x4.shared.b16 {%0,%1,%2,%3}, [%4];"
                 : "=r"(r[0]), "=r"(r[1]), "=r"(r[2]), "=r"(r[3]) : "r"(addr));
}
DEV_INLINE void mma16816(float* c, const uint32_t* a, const uint32_t* b) {
    asm volatile(
        "mma.sync.aligned.m16n8k16.row.col.f32.f16.f16.f32 "
        "{%0,%1,%2,%3}, {%4,%5,%6,%7}, {%8,%9}, {%0,%1,%2,%3};"
        : "+f"(c[0]), "+f"(c[1]), "+f"(c[2]), "+f"(c[3])
        : "r"(a[0]), "r"(a[1]), "r"(a[2]), "r"(a[3]), "r"(b[0]), "r"(b[1]));
}

// ---------------------------------------------------------------- kernel 1: DCT matrix
__global__ void build_c_kernel() {
    int idx = blockIdx.x * 256 + threadIdx.x;       // 0 .. 2^20-1
    int k = idx >> 10;
    int j = idx & 1023;
    // angle = pi*(2j+1)*k/2048; reduce to [-2048, 2048) -> ang in [-pi, pi) so __cosf is accurate
    int t = ((k * (2 * j + 1) + 2048) & 4095) - 2048;
    float ang = (float)t * 1.5339807878856412e-3f;  // pi/2048
    float s = (k == 0) ? 0.03125f : 0.04419417382415922f;  // 1/32, sqrt(2)/32
    d_C[idx] = __float2half(s * __cosf(ang));
}

// ---------------------------------------------------------------- kernel 2: transpose+fp16
// x[b][j][m] fp32 -> d_xt[b][m][j] fp16.  64-wide j tiles so the fp16 store side
// writes 128B per warp (full transactions).
__global__ void transpose_kernel(const float* __restrict__ x) {
    __shared__ float tile[64][33];
    int b = blockIdx.z;
    int m0 = blockIdx.x * 32, j0 = blockIdx.y * 64;
    const float* xb = x + ((size_t)b << 20);
    int tx = threadIdx.x, ty = threadIdx.y;
#pragma unroll
    for (int r = ty; r < 64; r += 8)
        tile[r][tx] = xb[(size_t)(j0 + r) * 1024 + m0 + tx];
    __syncthreads();
    __half2* xtb2 = (__half2*)(d_xt + ((size_t)b << 20));
#pragma unroll
    for (int r = ty; r < 32; r += 8) {
        __half2 v = __floats2half2_rn(tile[2 * tx][r], tile[2 * tx + 1][r]);
        xtb2[(((size_t)(m0 + r) * 1024 + j0) >> 1) + tx] = v;
    }
}

// ---------------------------------------------------------------- kernel 3: GEMM
// Out[k, n] = sum_j C[k, j] * xt[n, j]    (n = b*1024 + m)
DEV_INLINE void load_chunk(int q, int stage, int tid, int k0,
                           const __half* Bsrc, uint32_t sbase) {
    uint32_t abase = sbase + stage * STAGE_BYTES;
    uint32_t bbase = abase + A_STAGE_BYTES;
    int kc0 = q * BK;
    // A: 128 rows x 8 x 16B segs = 1024 segs; B: same. 128 threads -> 8 each.
#pragma unroll
    for (int i = 0; i < 8; i++) {
        int s = tid + i * THREADS;
        int row = s >> 3, seg = s & 7;
        cp16(abase + swz((uint32_t)(row * 128 + seg * 16)),
             (const void*)(d_C + (size_t)(k0 + row) * NDIM + kc0 + seg * 8));
    }
#pragma unroll
    for (int i = 0; i < 8; i++) {
        int s = tid + i * THREADS;
        int row = s >> 3, seg = s & 7;
        cp16(bbase + swz((uint32_t)(row * 128 + seg * 16)),
             (const void*)(Bsrc + (size_t)row * NDIM + kc0 + seg * 8));
    }
}

__global__ void __launch_bounds__(THREADS, 2) dct_gemm_kernel(float* __restrict__ out) {
    extern __shared__ char smem[];
    uint32_t sbase = smem_u32(smem);
    int tid = threadIdx.x;
    int lane = tid & 31, wid = tid >> 5;
    int warp_m = wid & 1;         // 2 m-warps (64 rows each)
    int warp_n = wid >> 1;        // 2 n-warps (64 cols each)

    int k0 = blockIdx.x * BM;                   // DCT row tile
    int b  = blockIdx.y >> 3;                   // 8 n-tiles per batch image
    int m0 = (blockIdx.y & 7) * BN;
    const __half* Bsrc = d_xt + ((size_t)b << 20) + (size_t)m0 * NDIM;

    float acc[4][8][4] = {};                    // [mi][ni][frag] : 64x64 warp tile

    // ldmatrix address components (tile = lane>>3, row-in-tile = lane&7)
    int a_row = warp_m * 64 + (lane & 7) + (((lane >> 3) & 1) << 3);
    int a_kx  = (lane >> 4) << 3;
    int b_row = warp_n * 64 + (lane & 7) + ((lane >> 4) << 3);
    int b_kx  = ((lane >> 3) & 1) << 3;

    // prologue: stages 0..STAGES-2
#pragma unroll
    for (int s = 0; s < STAGES - 1; s++) { load_chunk(s, s, tid, k0, Bsrc, sbase); cp_commit(); }

    for (int c = 0; c < NCHUNK; c++) {
        cp_wait<STAGES - 2>();               // chunk c resident (<=1 group pending)
        __syncthreads();                     // all threads see stage c; stage c-1 fully consumed

        int q = c + STAGES - 1;              // issue next loads BEFORE compute (overlap)
        if (q < NCHUNK) load_chunk(q, q % STAGES, tid, k0, Bsrc, sbase);
        cp_commit();                         // always commit (possibly empty group)

        uint32_t abase = sbase + (c % STAGES) * STAGE_BYTES;
        uint32_t bbase = abase + A_STAGE_BYTES;
#pragma unroll
        for (int ks = 0; ks < BK / 16; ks++) {
            uint32_t af[4][4];
#pragma unroll
            for (int mi = 0; mi < 4; mi++)
                ldsm4(af[mi], abase + swz((uint32_t)((a_row + mi * 16) * 128 +
                                                     (ks * 16 + a_kx) * 2)));
#pragma unroll
            for (int h = 0; h < 4; h++) {    // each ldsm4 feeds 2 n-frags
                uint32_t r[4];
                ldsm4(r, bbase + swz((uint32_t)((b_row + h * 16) * 128 +
                                                (ks * 16 + b_kx) * 2)));
#pragma unroll
                for (int mi = 0; mi < 4; mi++) {
                    mma16816(acc[mi][2 * h + 0], af[mi], r);
                    mma16816(acc[mi][2 * h + 1], af[mi], r + 2);
                }
            }
        }
    }

    __syncthreads();                         // last chunk consumed before staging reuse

    // epilogue: regs -> smem staging (stride 132, conflict-free) -> float4 stores
    float* stg = (float*)smem;
    int gr = lane >> 2, cl = (lane & 3) * 2;
#pragma unroll
    for (int mi = 0; mi < 4; mi++)
#pragma unroll
        for (int ni = 0; ni < 8; ni++) {
            int r0 = warp_m * 64 + mi * 16 + gr;
            int col = warp_n * 64 + ni * 8 + cl;
            stg[r0 * 132 + col]           = acc[mi][ni][0];
            stg[r0 * 132 + col + 1]       = acc[mi][ni][1];
            stg[(r0 + 8) * 132 + col]     = acc[mi][ni][2];
            stg[(r0 + 8) * 132 + col + 1] = acc[mi][ni][3];
        }
    __syncthreads();

    size_t ob = ((size_t)b << 20) + (size_t)k0 * 1024 + m0;
#pragma unroll
    for (int i = 0; i < 32; i++) {
        int idx = i * THREADS + tid;         // 4096 float4s = 128 rows x 32
        int row = idx >> 5;
        int c4 = (idx & 31) * 4;
        float4 v = *(const float4*)(stg + row * 132 + c4);
        *(float4*)(out + ob + (size_t)row * 1024 + c4) = v;
    }
}

// ---------------------------------------------------------------- launch
extern "C" void kernel_launch(void* const* d_in, const int* in_sizes, int n_in,
                              void* d_out, int out_size) {
    (void)in_sizes; (void)n_in; (void)out_size;
    const float* x = (const float*)d_in[0];
    float* out = (float*)d_out;

    build_c_kernel<<<(NDIM * NDIM) / 256, 256>>>();

    dim3 tg(32, 16, NBATCH), tb(32, 8);
    transpose_kernel<<<tg, tb>>>(x);

    cudaFuncSetAttribute(dct_gemm_kernel, cudaFuncAttributeMaxDynamicSharedMemorySize, SMEM_TOTAL);
    dim3 gg(NDIM / BM, (NBATCH * NDIM) / BN);   // (8, 256)
    dct_gemm_kernel<<<gg, THREADS, SMEM_TOTAL>>>(out);
}

// round 6
// speedup vs baseline: 1.6247x; 1.6247x over previous
#include <cuda_runtime.h>
#include <cuda_fp16.h>
#include <cstdint>

#define DEV_INLINE __device__ __forceinline__

static constexpr int NDIM   = 1024;   // DCT length (axis 1)
static constexpr int KDIM   = 512;    // halved K via even/odd symmetry
static constexpr int NBATCH = 32;

// GEMM tiling (portable mma.sync path — tcgen05 rejected by compute_103 PTX target)
static constexpr int BM = 128;        // DCT output rows per CTA (within one parity)
static constexpr int BN = 128;        // (b,m) columns per CTA
static constexpr int BK = 64;         // K per chunk (64 fp16 = 128 B = SW128 row)
static constexpr int NCHUNK = KDIM / BK;   // 8
static constexpr int STAGES = 3;
static constexpr int THREADS = 256;   // 8 warps: 2 (m) x 4 (n), warp tile 64x32 (proven R3 config)

static constexpr int A_STAGE_BYTES = BM * 128;              // 16 KB
static constexpr int STAGE_BYTES   = 2 * A_STAGE_BYTES;     // 32 KB (A + B)
static constexpr int SMEM_TOTAL    = STAGES * STAGE_BYTES;  // 96 KB (covers 128x132 f32 epilogue staging)

// Scratch (allocation-free rule: __device__ globals)
__device__ __half d_C2[2 * KDIM * KDIM];                   // [parity][r][j] folded DCT matrices
__device__ __half d_xs[(size_t)NBATCH * NDIM * KDIM];      // sum:  [b][m][j], j<512
__device__ __half d_xd[(size_t)NBATCH * NDIM * KDIM];      // diff: [b][m][j], j<512

// ---------------------------------------------------------------- helpers
DEV_INLINE uint32_t smem_u32(const void* p) {
    uint32_t a;
    asm("{ .reg .u64 t; cvta.to.shared.u64 t, %1; cvt.u32.u64 %0, t; }" : "=r"(a) : "l"(p));
    return a;
}
DEV_INLINE void cp16(uint32_t saddr, const void* g) {
    asm volatile("cp.async.cg.shared.global [%0], [%1], 16;" :: "r"(saddr), "l"(g));
}
DEV_INLINE void cp_commit() { asm volatile("cp.async.commit_group;"); }
template <int N> DEV_INLINE void cp_wait() { asm volatile("cp.async.wait_group %0;" :: "n"(N)); }
DEV_INLINE uint32_t swz(uint32_t off) { return off ^ ((off >> 3) & 0x70); }

DEV_INLINE void ldsm4(uint32_t* r, uint32_t addr) {
    asm volatile("ldmatrix.sync.aligned.m8n8.x4.shared.b16 {%0,%1,%2,%3}, [%4];"
                 : "=r"(r[0]), "=r"(r[1]), "=r"(r[2]), "=r"(r[3]) : "r"(addr));
}
DEV_INLINE void mma16816(float* c, const uint32_t* a, const uint32_t* b) {
    asm volatile(
        "mma.sync.aligned.m16n8k16.row.col.f32.f16.f16.f32 "
        "{%0,%1,%2,%3}, {%4,%5,%6,%7}, {%8,%9}, {%0,%1,%2,%3};"
        : "+f"(c[0]), "+f"(c[1]), "+f"(c[2]), "+f"(c[3])
        : "r"(a[0]), "r"(a[1]), "r"(a[2]), "r"(a[3]), "r"(b[0]), "r"(b[1]));
}

// ---------------------------------------------------------------- kernel 1: folded DCT matrices
// d_C2[p][r][j] = scale(2r+p) * cos(pi*(2j+1)*(2r+p)/2048), r<512, j<512
__global__ void build_c_kernel() {
    int idx = blockIdx.x * 256 + threadIdx.x;       // 0 .. 2*512*512-1
    int p = idx >> 18;
    int r = (idx >> 9) & 511;
    int j = idx & 511;
    int k = 2 * r + p;
    int t = ((k * (2 * j + 1) + 2048) & 4095) - 2048;   // angle in [-pi, pi)
    float ang = (float)t * 1.5339807878856412e-3f;      // pi/2048
    float s = (k == 0) ? 0.03125f : 0.04419417382415922f;  // 1/32, sqrt(2)/32
    d_C2[idx] = __float2half(s * __cosf(ang));
}

// ---------------------------------------------------------------- kernel 2: fold + transpose + fp16
// x[b][j][m] fp32 -> d_xs[b][m][j] = x[j]+x[1023-j], d_xd = x[j]-x[1023-j]  (j<512)
__global__ void transpose_kernel(const float* __restrict__ x) {
    __shared__ float tlo[64][33];
    __shared__ float thi[64][33];
    int b = blockIdx.z;
    int m0 = blockIdx.x * 32, j0 = blockIdx.y * 64;
    const float* xb = x + ((size_t)b << 20);
    int tx = threadIdx.x, ty = threadIdx.y;
#pragma unroll
    for (int r = ty; r < 64; r += 8) {
        tlo[r][tx] = xb[(size_t)(j0 + r) * 1024 + m0 + tx];
        thi[r][tx] = xb[(size_t)(1023 - j0 - r) * 1024 + m0 + tx];
    }
    __syncthreads();
    size_t base2 = (((size_t)b << 19) + (size_t)m0 * KDIM + j0) >> 1;   // in half2 units
    __half2* xs2 = (__half2*)d_xs + base2;
    __half2* xd2 = (__half2*)d_xd + base2;
#pragma unroll
    for (int r = ty; r < 32; r += 8) {       // r = m-row within tile, tx = j pair
        float a0 = tlo[2 * tx][r],     h0 = thi[2 * tx][r];
        float a1 = tlo[2 * tx + 1][r], h1 = thi[2 * tx + 1][r];
        size_t o = (size_t)r * (KDIM / 2) + tx;
        xs2[o] = __floats2half2_rn(a0 + h0, a1 + h1);
        xd2[o] = __floats2half2_rn(a0 - h0, a1 - h1);
    }
}

// ---------------------------------------------------------------- kernel 3: GEMM
// Out[2r+p, n] = sum_{j<512} C2[p][r, j] * xf[p][n, j]    (n = b*1024 + m)
DEV_INLINE void load_chunk(int q, int stage, int tid, const __half* Asrc,
                           const __half* Bsrc, uint32_t sbase) {
    uint32_t abase = sbase + stage * STAGE_BYTES;
    uint32_t bbase = abase + A_STAGE_BYTES;
    int kc0 = q * BK;
    // A: 128 rows x 8 x 16B segs = 1024 segs; B same. 256 threads -> 4 each.
#pragma unroll
    for (int i = 0; i < 4; i++) {
        int s = tid + i * THREADS;
        int row = s >> 3, seg = s & 7;
        cp16(abase + swz((uint32_t)(row * 128 + seg * 16)),
             (const void*)(Asrc + (size_t)row * KDIM + kc0 + seg * 8));
    }
#pragma unroll
    for (int i = 0; i < 4; i++) {
        int s = tid + i * THREADS;
        int row = s >> 3, seg = s & 7;
        cp16(bbase + swz((uint32_t)(row * 128 + seg * 16)),
             (const void*)(Bsrc + (size_t)row * KDIM + kc0 + seg * 8));
    }
}

__global__ void __launch_bounds__(THREADS, 2) dct_gemm_kernel(float* __restrict__ out) {
    extern __shared__ char smem[];
    uint32_t sbase = smem_u32(smem);
    int tid = threadIdx.x;
    int lane = tid & 31, wid = tid >> 5;
    int warp_m = wid & 1;         // 2 m-warps (64 rows)
    int warp_n = wid >> 1;        // 4 n-warps (32 cols)

    int parity = blockIdx.x & 1;
    int k0 = (blockIdx.x >> 1) * BM;            // row tile within this parity's 512
    int b  = blockIdx.y >> 3;                   // 8 n-tiles per batch image
    int m0 = (blockIdx.y & 7) * BN;
    const __half* Asrc = d_C2 + (size_t)parity * KDIM * KDIM + (size_t)k0 * KDIM;
    const __half* Bfold = parity ? d_xd : d_xs;
    const __half* Bsrc = Bfold + ((size_t)b << 19) + (size_t)m0 * KDIM;

    float acc[4][4][4] = {};                    // [mi][ni][frag] : 64x32 warp tile

    // ldmatrix address components (tile = lane>>3, row-in-tile = lane&7)
    int a_row = warp_m * 64 + (lane & 7) + (((lane >> 3) & 1) << 3);
    int a_kx  = (lane >> 4) << 3;
    int b_row = warp_n * 32 + (lane & 7) + ((lane >> 4) << 3);
    int b_kx  = ((lane >> 3) & 1) << 3;

    // prologue
#pragma unroll
    for (int s = 0; s < STAGES - 1; s++) { load_chunk(s, s, tid, Asrc, Bsrc, sbase); cp_commit(); }

    for (int c = 0; c < NCHUNK; c++) {
        int q = c + STAGES - 1;
        if (q < NCHUNK) load_chunk(q, q % STAGES, tid, Asrc, Bsrc, sbase);
        cp_commit();                         // always commit (possibly empty group)
        cp_wait<STAGES - 1>();               // chunk c complete
        __syncthreads();

        uint32_t abase = sbase + (c % STAGES) * STAGE_BYTES;
        uint32_t bbase = abase + A_STAGE_BYTES;
#pragma unroll
        for (int ks = 0; ks < BK / 16; ks++) {
            uint32_t af[4][4];
#pragma unroll
            for (int mi = 0; mi < 4; mi++)
                ldsm4(af[mi], abase + swz((uint32_t)((a_row + mi * 16) * 128 +
                                                     (ks * 16 + a_kx) * 2)));
            uint32_t bf[4][2];
#pragma unroll
            for (int h = 0; h < 2; h++) {
                uint32_t r[4];
                ldsm4(r, bbase + swz((uint32_t)((b_row + h * 16) * 128 +
                                                (ks * 16 + b_kx) * 2)));
                bf[2 * h + 0][0] = r[0]; bf[2 * h + 0][1] = r[1];
                bf[2 * h + 1][0] = r[2]; bf[2 * h + 1][1] = r[3];
            }
#pragma unroll
            for (int mi = 0; mi < 4; mi++)
#pragma unroll
                for (int ni = 0; ni < 4; ni++)
                    mma16816(acc[mi][ni], af[mi], bf[ni]);
        }
        __syncthreads();                     // before next iter overwrites this stage
    }

    // epilogue: regs -> smem staging (stride 132) -> float4 stores, output row stride 2
    float* stg = (float*)smem;
    int gr = lane >> 2, cl = (lane & 3) * 2;
#pragma unroll
    for (int mi = 0; mi < 4; mi++)
#pragma unroll
        for (int ni = 0; ni < 4; ni++) {
            int r0 = warp_m * 64 + mi * 16 + gr;
            int col = warp_n * 32 + ni * 8 + cl;
            stg[r0 * 132 + col]           = acc[mi][ni][0];
            stg[r0 * 132 + col + 1]       = acc[mi][ni][1];
            stg[(r0 + 8) * 132 + col]     = acc[mi][ni][2];
            stg[(r0 + 8) * 132 + col + 1] = acc[mi][ni][3];
        }
    __syncthreads();

    // global row for local rr: 2*(k0+rr) + parity
    size_t ob = ((size_t)b << 20) + ((size_t)(2 * k0 + parity)) * 1024 + m0;
#pragma unroll
    for (int i = 0; i < 16; i++) {
        int idx = i * THREADS + tid;         // 4096 float4s = 128 rows x 32
        int row = idx >> 5;
        int c4 = (idx & 31) * 4;
        float4 v = *(const float4*)(stg + row * 132 + c4);
        *(float4*)(out + ob + (size_t)row * 2048 + c4) = v;
    }
}

// ---------------------------------------------------------------- launch
extern "C" void kernel_launch(void* const* d_in, const int* in_sizes, int n_in,
                              void* d_out, int out_size) {
    (void)in_sizes; (void)n_in; (void)out_size;
    const float* x = (const float*)d_in[0];
    float* out = (float*)d_out;

    build_c_kernel<<<(2 * KDIM * KDIM) / 256, 256>>>();

    dim3 tg(32, 8, NBATCH), tb(32, 8);
    transpose_kernel<<<tg, tb>>>(x);

    cudaFuncSetAttribute(dct_gemm_kernel, cudaFuncAttributeMaxDynamicSharedMemorySize, SMEM_TOTAL);
    dim3 gg(2 * KDIM / BM, (NBATCH * NDIM) / BN);   // (8, 256)
    dct_gemm_kernel<<<gg, THREADS, SMEM_TOTAL>>>(out);
}

// round 10
// speedup vs baseline: 1.6511x; 1.0163x over previous
#include <cuda_runtime.h>
#include <cuda_fp16.h>
#include <cstdint>

#define DEV_INLINE __device__ __forceinline__

static constexpr int NDIM   = 1024;
static constexpr int NBATCH = 32;

// GEMM tiling (portable mma.sync; tcgen05 rejected by compute_103 PTX target)
static constexpr int BM = 128;
static constexpr int BN = 128;
static constexpr int BK = 64;         // 64 fp16 = 128 B
static constexpr int STAGES = 3;
static constexpr int THREADS = 256;   // 8 warps: 2(m) x 4(n), warp tile 64x32 (proven config)

static constexpr int A_STAGE_BYTES = BM * 128;              // 16 KB
static constexpr int STAGE_BYTES   = 2 * A_STAGE_BYTES;     // 32 KB
static constexpr int SMEM_TOTAL    = STAGES * STAGE_BYTES;  // 96 KB

// Folded DCT (level 2 on the even branch):
//   odd rows  k=2r+1: Out = Codd(512x512) @ d    d[j]  = x[j]-x[1023-j]           (j<512)
//   rows k=4t:        Out = Cee (256x256) @ ss   ss[j] = s[j]+s[511-j]            (j<256)
//   rows k=4t+2:      Out = Ceo (256x256) @ sd   sd[j] = s[j]-s[511-j]
//   with s[j] = x[j]+x[1023-j]
__device__ __half d_Codd[512 * 512];
__device__ __half d_Cee[256 * 256];
__device__ __half d_Ceo[256 * 256];
__device__ __half d_xd [(size_t)NBATCH * 1024 * 512];   // [b][m][j<512]  (K-contig)
__device__ __half d_xss[(size_t)NBATCH * 1024 * 256];   // [b][m][j<256]
__device__ __half d_xsd[(size_t)NBATCH * 1024 * 256];

// ---------------------------------------------------------------- helpers
DEV_INLINE uint32_t smem_u32(const void* p) {
    uint32_t a;
    asm("{ .reg .u64 t; cvta.to.shared.u64 t, %1; cvt.u32.u64 %0, t; }" : "=r"(a) : "l"(p));
    return a;
}
DEV_INLINE void cp16(uint32_t saddr, const void* g) {
    asm volatile("cp.async.cg.shared.global [%0], [%1], 16;" :: "r"(saddr), "l"(g));
}
DEV_INLINE void cp_commit() { asm volatile("cp.async.commit_group;"); }
template <int N> DEV_INLINE void cp_wait() { asm volatile("cp.async.wait_group %0;" :: "n"(N)); }
DEV_INLINE uint32_t swz(uint32_t off) { return off ^ ((off >> 3) & 0x70); }

DEV_INLINE void ldsm4(uint32_t* r, uint32_t addr) {
    asm volatile("ldmatrix.sync.aligned.m8n8.x4.shared.b16 {%0,%1,%2,%3}, [%4];"
                 : "=r"(r[0]), "=r"(r[1]), "=r"(r[2]), "=r"(r[3]) : "r"(addr));
}
DEV_INLINE void mma16816(float* c, const uint32_t* a, const uint32_t* b) {
    asm volatile(
        "mma.sync.aligned.m16n8k16.row.col.f32.f16.f16.f32 "
        "{%0,%1,%2,%3}, {%4,%5,%6,%7}, {%8,%9}, {%0,%1,%2,%3};"
        : "+f"(c[0]), "+f"(c[1]), "+f"(c[2]), "+f"(c[3])
        : "r"(a[0]), "r"(a[1]), "r"(a[2]), "r"(a[3]), "r"(b[0]), "r"(b[1]));
}

// ---------------------------------------------------------------- kernel 1: DCT matrices
// entry = scale(k) * cos(pi * ((2j+1)k mod 4096) / 2048)
__global__ void build_c_kernel() {
    int idx = blockIdx.x * 256 + threadIdx.x;   // 0 .. 393215
    int k, j;
    __half* dst;
    if (idx < 262144) {                         // Codd: r<512, j<512, k=2r+1
        j = idx & 511; k = 2 * (idx >> 9) + 1; dst = d_Codd + idx;
    } else if (idx < 327680) {                  // Cee: t<256, j<256, k=4t
        int l = idx - 262144;
        j = l & 255; k = 4 * (l >> 8); dst = d_Cee + l;
    } else {                                    // Ceo: k=4t+2
        int l = idx - 327680;
        j = l & 255; k = 4 * (l >> 8) + 2; dst = d_Ceo + l;
    }
    int t = ((k * (2 * j + 1) + 2048) & 4095) - 2048;   // angle -> [-pi, pi)
    float ang = (float)t * 1.5339807878856412e-3f;      // pi/2048
    float s = (k == 0) ? 0.03125f : 0.04419417382415922f;
    *dst = __float2half(s * __cosf(ang));
}

// ---------------------------------------------------------------- kernel 2: fold + transpose
// Block handles m-tile (32) x jj-tile (64), jj<256. Reads x row-groups jj, 1023-jj,
// 511-jj, 512+jj; writes d (rows jj and 511-jj), ss, sd in [b][m][j] K-contig layout.
__global__ void fold_kernel(const float* __restrict__ x) {
    __shared__ float tA[64][33], tB[64][33], tC[64][33], tD[64][33];
    int b = blockIdx.z;
    int m0 = blockIdx.x * 32, jj0 = blockIdx.y * 64;    // jj0 in {0,64,128,192}
    const float* xb = x + ((size_t)b << 20);
    int tx = threadIdx.x, ty = threadIdx.y;
#pragma unroll
    for (int r = ty; r < 64; r += 8) {
        tA[r][tx] = xb[(size_t)(jj0 + r) * 1024 + m0 + tx];
        tB[r][tx] = xb[(size_t)(1023 - jj0 - r) * 1024 + m0 + tx];
        tC[r][tx] = xb[(size_t)(511 - jj0 - r) * 1024 + m0 + tx];
        tD[r][tx] = xb[(size_t)(512 + jj0 + r) * 1024 + m0 + tx];
    }
    __syncthreads();
    int jd0 = 448 - jj0;                        // d[511-jj] lands in [jd0, jd0+64)
    __half2* xd2  = (__half2*)d_xd;
    __half2* xss2 = (__half2*)d_xss;
    __half2* xsd2 = (__half2*)d_xsd;
#pragma unroll
    for (int r = ty; r < 32; r += 8) {          // r = m-row within tile; tx = j-pair
        size_t rowd = ((size_t)b * 1024 + m0 + r) * 256;   // d_xd row in half2 units
        size_t rows = ((size_t)b * 1024 + m0 + r) * 128;   // ss/sd row in half2 units
        float a0 = tA[2 * tx][r],     b0 = tB[2 * tx][r];
        float a1 = tA[2 * tx + 1][r], b1 = tB[2 * tx + 1][r];
        float c0 = tC[2 * tx][r],     e0 = tD[2 * tx][r];
        float c1 = tC[2 * tx + 1][r], e1 = tD[2 * tx + 1][r];
        // d[jj] = x[jj]-x[1023-jj]
        xd2[rowd + (jj0 >> 1) + tx] = __floats2half2_rn(a0 - b0, a1 - b1);
        // d[511-jj] = x[511-jj]-x[512+jj], reversed within tile (rr = 63-2tx, 62-2tx)
        float ch0 = tC[63 - 2 * tx][r], eh0 = tD[63 - 2 * tx][r];
        float ch1 = tC[62 - 2 * tx][r], eh1 = tD[62 - 2 * tx][r];
        xd2[rowd + (jd0 >> 1) + tx] = __floats2half2_rn(ch0 - eh0, ch1 - eh1);
        // ss/sd: s[jj] = a+b, s[511-jj] = c+e
        float slo0 = a0 + b0, shi0 = c0 + e0;
        float slo1 = a1 + b1, shi1 = c1 + e1;
        xss2[rows + (jj0 >> 1) + tx] = __floats2half2_rn(slo0 + shi0, slo1 + shi1);
        xsd2[rows + (jj0 >> 1) + tx] = __floats2half2_rn(slo0 - shi0, slo1 - shi1);
    }
}

// ---------------------------------------------------------------- kernel 3: GEMM (R6-proven)
// Out[ROWMUL*(k0+rr)+ROWOFF, n] = sum_{j<KD} A[k0+rr, j] * B[n, j]   (n = b*1024+m)
// A/B selected from __device__ globals IN DEVICE CODE (host code cannot pass
// __device__ symbols as launch args — that was the R7/R8 failure).
template <int KD>
DEV_INLINE void load_chunk(int q, int stage, int tid, const __half* Asrc,
                           const __half* Bsrc, uint32_t sbase) {
    uint32_t abase = sbase + stage * STAGE_BYTES;
    uint32_t bbase = abase + A_STAGE_BYTES;
    int kc0 = q * BK;
#pragma unroll
    for (int i = 0; i < 4; i++) {
        int s = tid + i * THREADS;
        int row = s >> 3, seg = s & 7;
        cp16(abase + swz((uint32_t)(row * 128 + seg * 16)),
             (const void*)(Asrc + (size_t)row * KD + kc0 + seg * 8));
    }
#pragma unroll
    for (int i = 0; i < 4; i++) {
        int s = tid + i * THREADS;
        int row = s >> 3, seg = s & 7;
        cp16(bbase + swz((uint32_t)(row * 128 + seg * 16)),
             (const void*)(Bsrc + (size_t)row * KD + kc0 + seg * 8));
    }
}

template <int KD, int SEL, int ROWMUL, int ROWOFF>
__global__ void __launch_bounds__(THREADS, 2) gemm_kernel(float* __restrict__ out) {
    constexpr int NCH = KD / BK;
    extern __shared__ char smem[];
    uint32_t sbase = smem_u32(smem);
    int tid = threadIdx.x;
    int lane = tid & 31, wid = tid >> 5;
    int warp_m = wid & 1;          // 2 m-warps (64 rows)
    int warp_n = wid >> 1;         // 4 n-warps (32 cols)

    // device-side selection of operand globals
    const __half* Amat = (SEL == 0) ? d_Codd : (SEL == 1) ? d_Cee : d_Ceo;
    const __half* Bmat = (SEL == 0) ? d_xd   : (SEL == 1) ? d_xss : d_xsd;

    int k0 = blockIdx.x * BM;
    int b  = blockIdx.y >> 3;
    int m0 = (blockIdx.y & 7) * BN;
    const __half* Apanel = Amat + (size_t)k0 * KD;
    const __half* Bpanel = Bmat + ((size_t)b * 1024 + m0) * KD;

    float acc[4][4][4] = {};

    // ldmatrix address components (proven mapping, both operands non-trans)
    int a_row = warp_m * 64 + (lane & 7) + (((lane >> 3) & 1) << 3);
    int a_kx  = (lane >> 4) << 3;
    int b_row = warp_n * 32 + (lane & 7) + ((lane >> 4) << 3);
    int b_kx  = ((lane >> 3) & 1) << 3;

#pragma unroll
    for (int s = 0; s < STAGES - 1; s++) {
        load_chunk<KD>(s, s, tid, Apanel, Bpanel, sbase); cp_commit();
    }

    for (int c = 0; c < NCH; c++) {
        int q = c + STAGES - 1;
        if (q < NCH) load_chunk<KD>(q, q % STAGES, tid, Apanel, Bpanel, sbase);
        cp_commit();
        cp_wait<STAGES - 1>();
        __syncthreads();

        uint32_t abase = sbase + (c % STAGES) * STAGE_BYTES;
        uint32_t bbase = abase + A_STAGE_BYTES;
#pragma unroll
        for (int ks = 0; ks < BK / 16; ks++) {
            uint32_t af[4][4];
#pragma unroll
            for (int mi = 0; mi < 4; mi++)
                ldsm4(af[mi], abase + swz((uint32_t)((a_row + mi * 16) * 128 +
                                                     (ks * 16 + a_kx) * 2)));
            uint32_t bf[4][2];
#pragma unroll
            for (int h = 0; h < 2; h++) {
                uint32_t r[4];
                ldsm4(r, bbase + swz((uint32_t)((b_row + h * 16) * 128 +
                                                (ks * 16 + b_kx) * 2)));
                bf[2 * h + 0][0] = r[0]; bf[2 * h + 0][1] = r[1];
                bf[2 * h + 1][0] = r[2]; bf[2 * h + 1][1] = r[3];
            }
#pragma unroll
            for (int mi = 0; mi < 4; mi++)
#pragma unroll
                for (int ni = 0; ni < 4; ni++)
                    mma16816(acc[mi][ni], af[mi], bf[ni]);
        }
        __syncthreads();
    }

    // epilogue: regs -> smem (stride 132) -> float4 stores, output row stride ROWMUL*1024
    float* stg = (float*)smem;
    int gr = lane >> 2, cl = (lane & 3) * 2;
#pragma unroll
    for (int mi = 0; mi < 4; mi++)
#pragma unroll
        for (int ni = 0; ni < 4; ni++) {
            int r0 = warp_m * 64 + mi * 16 + gr;
            int col = warp_n * 32 + ni * 8 + cl;
            stg[r0 * 132 + col]           = acc[mi][ni][0];
            stg[r0 * 132 + col + 1]       = acc[mi][ni][1];
            stg[(r0 + 8) * 132 + col]     = acc[mi][ni][2];
            stg[(r0 + 8) * 132 + col + 1] = acc[mi][ni][3];
        }
    __syncthreads();

    size_t ob = ((size_t)b << 20) + (size_t)(ROWMUL * k0 + ROWOFF) * 1024 + m0;
    constexpr size_t rstride = (size_t)ROWMUL * 1024;
#pragma unroll
    for (int i = 0; i < 16; i++) {
        int idx = i * THREADS + tid;         // 4096 float4s = 128 rows x 32
        int row = idx >> 5;
        int c4 = (idx & 31) * 4;
        float4 v = *(const float4*)(stg + row * 132 + c4);
        *(float4*)(out + ob + (size_t)row * rstride + c4) = v;
    }
}

// ---------------------------------------------------------------- launch
extern "C" void kernel_launch(void* const* d_in, const int* in_sizes, int n_in,
                              void* d_out, int out_size) {
    (void)in_sizes; (void)n_in; (void)out_size;
    const float* x = (const float*)d_in[0];
    float* out = (float*)d_out;

    build_c_kernel<<<1536, 256>>>();

    dim3 fg(32, 4, NBATCH), fb(32, 8);
    fold_kernel<<<fg, fb>>>(x);

    cudaFuncSetAttribute(gemm_kernel<512, 0, 2, 1>,
                         cudaFuncAttributeMaxDynamicSharedMemorySize, SMEM_TOTAL);
    cudaFuncSetAttribute(gemm_kernel<256, 1, 4, 0>,
                         cudaFuncAttributeMaxDynamicSharedMemorySize, SMEM_TOTAL);
    cudaFuncSetAttribute(gemm_kernel<256, 2, 4, 2>,
                         cudaFuncAttributeMaxDynamicSharedMemorySize, SMEM_TOTAL);

    // odd rows (2r+1): 512x512 @ d
    gemm_kernel<512, 0, 2, 1><<<dim3(4, 256), THREADS, SMEM_TOTAL>>>(out);
    // rows 4t: 256x256 @ ss
    gemm_kernel<256, 1, 4, 0><<<dim3(2, 256), THREADS, SMEM_TOTAL>>>(out);
    // rows 4t+2: 256x256 @ sd
    gemm_kernel<256, 2, 4, 2><<<dim3(2, 256), THREADS, SMEM_TOTAL>>>(out);
}